// round 9
// baseline (speedup 1.0000x reference)
#include <cuda_runtime.h>
#include <math.h>

// out[i] = F(x[i]) for a fixed smooth scalar F (weights shared across elems).
// Kernel 1: warp-per-entry exact tabulation of F on [-6.5, 6.5] (1024 nodes),
//           stored as overlapping float2 pairs; fires PDL trigger when done.
// Kernel 2: streaming LINEAR interpolation, 8KB smem table, 1184 blocks
//           (8 CTAs/SM full residency); PDL-overlapped with kernel 1:
//           front-batches x loads, then griddepcontrol.wait, then stages table.

#define HH 20
#define GG 80
#define LN_EPS 1e-5f

#define TAB_N 1024
#define TAB_XMIN (-6.5f)
#define TAB_XMAX (6.5f)
#define TAB_STEP ((TAB_XMAX - TAB_XMIN) / (float)(TAB_N - 1))
#define TAB_INV_STEP ((float)(TAB_N - 1) / (TAB_XMAX - TAB_XMIN))
#define TAB_T_OFF (-(TAB_XMIN) * TAB_INV_STEP)
#define TAB_T_MAX ((float)(TAB_N - 1) - 0.001f)

__device__ float2 g_tab2[TAB_N];   // g_tab2[j] = {tab[j], tab[j+1]}

struct Weights {
    const float *W1, *b1, *g1, *be1;
    const float *Wih0, *gi0, *bi0, *bh0, *go0, *bo0;
    const float *Wih1, *gi1, *bi1, *bh1, *go1, *bo1;
    const float *Wout, *bout;
};

__device__ __forceinline__ float fast_sigmoid(float z) {
    return 1.0f / (1.0f + __expf(-z));
}
__device__ __forceinline__ float fast_tanh(float z) {
    return 1.0f - 2.0f / (1.0f + __expf(2.0f * z));
}
__device__ __forceinline__ float warp_sum(float v) {
#pragma unroll
    for (int off = 16; off; off >>= 1) v += __shfl_xor_sync(0xffffffffu, v, off);
    return v;
}

// ===================== kernel 1: warp-per-entry table build =================
#define BUILD_WARPS 4
#define WPITCH 21
#define WROWS  96

__device__ __forceinline__ float cell_warp(const float* __restrict__ v,
                                           const float* __restrict__ Wsm,
                                           const float* gi, const float* bi,
                                           const float* bh, const float* go,
                                           const float* bo, float* gbuf,
                                           int lane) {
    const bool v2 = lane < 16;
    const bool act = lane < HH;
    const float* w0 = Wsm + lane * WPITCH;
    const float* w1 = Wsm + (32 + lane) * WPITCH;
    const float* w2 = Wsm + (64 + lane) * WPITCH;  // rows >= 80 are zero
    float a0 = 0.f, a1 = 0.f, a2 = 0.f;
#pragma unroll
    for (int k = 0; k < HH; k++) {
        a0 = fmaf(v[k], w0[k], a0);
        a1 = fmaf(v[k], w1[k], a1);
        a2 = fmaf(v[k], w2[k], a2);
    }
    float mu = warp_sum(a0 + a1 + a2) * (1.f / 80.f);
    float d0 = a0 - mu, d1 = a1 - mu, d2 = v2 ? (a2 - mu) : 0.f;
    float var = warp_sum(fmaf(d0, d0, fmaf(d1, d1, d2 * d2))) * (1.f / 79.f);
    float inv = 1.f / (sqrtf(var) + LN_EPS);
    gbuf[lane]      = d0 * inv * gi[lane]      + bi[lane]      + bh[lane];
    gbuf[32 + lane] = d1 * inv * gi[32 + lane] + bi[32 + lane] + bh[32 + lane];
    if (v2)
        gbuf[64 + lane] = d2 * inv * gi[64 + lane] + bi[64 + lane] + bh[64 + lane];
    __syncwarp();
    float c = 0.f, ov = 0.f;
    if (act) {
        float iv = gbuf[lane];
        ov = gbuf[40 + lane];
        float gv = gbuf[60 + lane];
        c = fast_sigmoid(iv) * fast_tanh(gv);
    }
    __syncwarp();
    float mu2 = warp_sum(c) * (1.f / 20.f);
    float dc = act ? (c - mu2) : 0.f;
    float var2 = warp_sum(dc * dc) * (1.f / 19.f);
    float inv2 = 1.f / (sqrtf(var2) + LN_EPS);
    float h = 0.f;
    if (act) {
        float cn = dc * inv2 * go[lane] + bo[lane];
        h = fast_sigmoid(ov) * fast_tanh(cn);
    }
    return h;
}

__global__ void __launch_bounds__(32 * BUILD_WARPS)
build_table_kernel(Weights w) {
    __shared__ float Wih0_s[WROWS * WPITCH];
    __shared__ float Wih1_s[WROWS * WPITCH];
    __shared__ float gates_s[BUILD_WARPS][GG];
    __shared__ float hx_s[BUILD_WARPS][HH];

    int tid = threadIdx.x;
    for (int idx = tid; idx < WROWS * WPITCH; idx += blockDim.x) {
        int r = idx / WPITCH, k = idx - r * WPITCH;
        float v0 = 0.f, v1 = 0.f;
        if (r < GG && k < HH) { v0 = w.Wih0[r * HH + k]; v1 = w.Wih1[r * HH + k]; }
        Wih0_s[idx] = v0;
        Wih1_s[idx] = v1;
    }
    __syncthreads();

    int warp = tid >> 5, lane = tid & 31;
    int entry = blockIdx.x * BUILD_WARPS + warp;
    float x = fmaf((float)entry, TAB_STEP, TAB_XMIN);
    const bool act = lane < HH;

    // layer 1
    float hval = 0.f;
    if (act) hval = fmaf(x, w.W1[lane], w.b1[lane]);
    {
        float mu = warp_sum(act ? hval : 0.f) * (1.f / 20.f);
        float d = act ? (hval - mu) : 0.f;
        float var = warp_sum(d * d) * (1.f / 19.f);
        float inv = 1.f / (sqrtf(var) + LN_EPS);
        if (act) hval = fast_tanh(d * inv * w.g1[lane] + w.be1[lane]);
    }

    float v[HH];
    if (act) hx_s[warp][lane] = hval;
    __syncwarp();
#pragma unroll
    for (int k = 0; k < HH; k++) v[k] = hx_s[warp][k];
    __syncwarp();

    hval = cell_warp(v, Wih0_s, w.gi0, w.bi0, w.bh0, w.go0, w.bo0,
                     gates_s[warp], lane);

    if (act) hx_s[warp][lane] = hval;
    __syncwarp();
#pragma unroll
    for (int k = 0; k < HH; k++) v[k] = hx_s[warp][k];
    __syncwarp();

    hval = cell_warp(v, Wih1_s, w.gi1, w.bi1, w.bh1, w.go1, w.bo1,
                     gates_s[warp], lane);

    float p = act ? hval * w.Wout[lane] : 0.f;
    p = warp_sum(p);
    if (lane == 0) {
        float val = p + w.bout[0];
        g_tab2[entry].x = val;
        if (entry > 0) g_tab2[entry - 1].y = val;
        if (entry == TAB_N - 1) g_tab2[entry].y = val;   // defined, never read
    }
    // PDL: allow the dependent interp kernel to begin launching
    asm volatile("griddepcontrol.launch_dependents;");
}

// ===================== kernel 2: smem-table linear interpolation ============
__device__ __forceinline__ float interp_one_s(float x, const float2* tab_s) {
    float t = fmaf(x, TAB_INV_STEP, TAB_T_OFF);
    t = fminf(fmaxf(t, 0.0f), TAB_T_MAX);      // clamp in t-space
    int i = __float2int_rd(t);
    float s = t - (float)i;
    float2 q = tab_s[i];                        // one LDS.64 (random banks)
    return fmaf(s, q.y - q.x, q.x);
}

#define VPT 4          // k-strided float4 batches per thread
#define IBLOCKS 1184   // 8 CTAs/SM x 148 SMs -> full residency in one wave

__global__ void __launch_bounds__(256)
interp_kernel(const float4* __restrict__ x4, float4* __restrict__ o4, int n4,
              const float* __restrict__ x, float* __restrict__ out, int n) {
    __shared__ float2 tab_s[TAB_N];

    int gtid = blockIdx.x * 256 + threadIdx.x;
    int stride = gridDim.x * 256;

    // 1) front-batch global x loads — independent of the table (overlaps PDL)
    float4 xv[VPT];
    bool vld[VPT];
#pragma unroll
    for (int k = 0; k < VPT; k++) {
        int idx = gtid + k * stride;
        vld[k] = idx < n4;
        if (vld[k]) xv[k] = __ldcs(&x4[idx]);
    }

    // 2) wait for the producer kernel's writes (PDL), then stage the table
    asm volatile("griddepcontrol.wait;");
    {
        const float4* src = (const float4*)g_tab2;
        float4* dst = (float4*)tab_s;
#pragma unroll
        for (int j = 0; j < TAB_N / 2 / 256; j++)
            dst[threadIdx.x + j * 256] = src[threadIdx.x + j * 256];
    }
    __syncthreads();

    // 3) interpolate + stream out
#pragma unroll
    for (int k = 0; k < VPT; k++) {
        if (!vld[k]) continue;
        float4 ov;
        ov.x = interp_one_s(xv[k].x, tab_s);
        ov.y = interp_one_s(xv[k].y, tab_s);
        ov.z = interp_one_s(xv[k].z, tab_s);
        ov.w = interp_one_s(xv[k].w, tab_s);
        __stcs(&o4[gtid + k * stride], ov);
    }

    // n % 4 tail
    if (blockIdx.x == 0 && threadIdx.x < 32) {
        for (int i = n4 * 4 + threadIdx.x; i < n; i += 32)
            out[i] = interp_one_s(x[i], tab_s);
    }
}

extern "C" void kernel_launch(void* const* d_in, const int* in_sizes, int n_in,
                              void* d_out, int out_size) {
    Weights w;
    w.W1 = (const float*)d_in[1];
    w.b1 = (const float*)d_in[2];
    w.g1 = (const float*)d_in[3];
    w.be1 = (const float*)d_in[4];
    w.Wih0 = (const float*)d_in[5];
    w.gi0 = (const float*)d_in[7];
    w.bi0 = (const float*)d_in[8];
    w.bh0 = (const float*)d_in[10];
    w.go0 = (const float*)d_in[11];
    w.bo0 = (const float*)d_in[12];
    w.Wih1 = (const float*)d_in[13];
    w.gi1 = (const float*)d_in[15];
    w.bi1 = (const float*)d_in[16];
    w.bh1 = (const float*)d_in[18];
    w.go1 = (const float*)d_in[19];
    w.bo1 = (const float*)d_in[20];
    w.Wout = (const float*)d_in[21];
    w.bout = (const float*)d_in[22];

    const float* x = (const float*)d_in[0];
    float* out = (float*)d_out;
    int n = in_sizes[0];
    int n4 = n / 4;

    build_table_kernel<<<TAB_N / BUILD_WARPS, 32 * BUILD_WARPS>>>(w);

    // full-residency grid; k-strided guards make any n safe. If n4 ever
    // exceeds IBLOCKS coverage, fall back to a covering grid.
    int blocks = IBLOCKS;
    if ((long long)blocks * 256 * VPT < (long long)n4)
        blocks = (int)(((long long)n4 + 256LL * VPT - 1) / (256LL * VPT));

    // PDL launch: interp may begin (and run its x-load preamble) while
    // build_table_kernel is still completing.
    cudaLaunchConfig_t cfg = {};
    cfg.gridDim = dim3((unsigned)blocks, 1, 1);
    cfg.blockDim = dim3(256, 1, 1);
    cfg.dynamicSmemBytes = 0;
    cudaLaunchAttribute attrs[1];
    attrs[0].id = cudaLaunchAttributeProgrammaticStreamSerialization;
    attrs[0].val.programmaticStreamSerializationAllowed = 1;
    cfg.attrs = attrs;
    cfg.numAttrs = 1;
    cfg.stream = 0;

    cudaError_t err = cudaLaunchKernelEx(&cfg, interp_kernel,
                                         (const float4*)x, (float4*)out, n4,
                                         x, out, n);
    if (err != cudaSuccess) {
        // fallback: plain launch (serialized)
        interp_kernel<<<blocks, 256>>>((const float4*)x, (float4*)out, n4,
                                       x, out, n);
    }
}

// round 11
// speedup vs baseline: 1.0113x; 1.0113x over previous
#include <cuda_runtime.h>
#include <cuda_fp16.h>
#include <stdint.h>
#include <math.h>

// out[i] = F(x[i]) for a fixed smooth scalar F (weights shared across elems).
// SINGLE fused kernel:
//   blocks 0..127: exact warp-per-entry tabulation of F (1024 nodes, half2
//                  pairs {F[j],F[j+1]}), then arrive on a device counter.
//   all blocks:    front-batch x loads (non-builders, overlaps the build),
//                  spin-wait for the table, stage 4KB into smem, then
//                  streaming linear interpolation (one LDS.32 per element).
// Deadlock-safety: builders are block-ids 0..127 (always wave 1); the barrier
// counter is reset only by the LAST block to exit, so no live block can
// observe a reset counter before passing the barrier.

#define HH 20
#define GG 80
#define LN_EPS 1e-5f

#define TAB_N 1024
#define TAB_XMIN (-6.5f)
#define TAB_XMAX (6.5f)
#define TAB_STEP ((TAB_XMAX - TAB_XMIN) / (float)(TAB_N - 1))
#define TAB_INV_STEP ((float)(TAB_N - 1) / (TAB_XMAX - TAB_XMIN))
#define TAB_T_OFF (-(TAB_XMIN) * TAB_INV_STEP)
#define TAB_T_MAX ((float)(TAB_N - 1) - 0.001f)

#define NBUILD 128       // builder blocks (8 entries each)
#define VPT 4            // k-strided float4 batches per thread
#define IBLOCKS 1184     // 8 CTAs/SM x 148 SMs

__device__ __half2 g_tab_h2[TAB_N];   // {F[j], F[j+1]}
__device__ volatile int g_count;      // build-arrival counter (reset each run)
__device__ int g_exit;                // exit counter for the reset

struct Weights {
    const float *W1, *b1, *g1, *be1;
    const float *Wih0, *gi0, *bi0, *bh0, *go0, *bo0;
    const float *Wih1, *gi1, *bi1, *bh1, *go1, *bo1;
    const float *Wout, *bout;
};

__device__ __forceinline__ float fast_sigmoid(float z) {
    return 1.0f / (1.0f + __expf(-z));
}
__device__ __forceinline__ float fast_tanh(float z) {
    return 1.0f - 2.0f / (1.0f + __expf(2.0f * z));
}
__device__ __forceinline__ float warp_sum(float v) {
#pragma unroll
    for (int off = 16; off; off >>= 1) v += __shfl_xor_sync(0xffffffffu, v, off);
    return v;
}

// ---------------- build helpers (warp-collective LN-LSTM cell) --------------
#define WPITCH 21
#define WROWS  96

__device__ __forceinline__ float cell_warp(const float* __restrict__ v,
                                           const float* __restrict__ Wsm,
                                           const float* gi, const float* bi,
                                           const float* bh, const float* go,
                                           const float* bo, float* gbuf,
                                           int lane) {
    const bool v2 = lane < 16;
    const bool act = lane < HH;
    const float* w0 = Wsm + lane * WPITCH;
    const float* w1 = Wsm + (32 + lane) * WPITCH;
    const float* w2 = Wsm + (64 + lane) * WPITCH;  // rows >= 80 are zero
    float a0 = 0.f, a1 = 0.f, a2 = 0.f;
#pragma unroll
    for (int k = 0; k < HH; k++) {
        a0 = fmaf(v[k], w0[k], a0);
        a1 = fmaf(v[k], w1[k], a1);
        a2 = fmaf(v[k], w2[k], a2);
    }
    float mu = warp_sum(a0 + a1 + a2) * (1.f / 80.f);
    float d0 = a0 - mu, d1 = a1 - mu, d2 = v2 ? (a2 - mu) : 0.f;
    float var = warp_sum(fmaf(d0, d0, fmaf(d1, d1, d2 * d2))) * (1.f / 79.f);
    float inv = 1.f / (sqrtf(var) + LN_EPS);
    gbuf[lane]      = d0 * inv * gi[lane]      + bi[lane]      + bh[lane];
    gbuf[32 + lane] = d1 * inv * gi[32 + lane] + bi[32 + lane] + bh[32 + lane];
    if (v2)
        gbuf[64 + lane] = d2 * inv * gi[64 + lane] + bi[64 + lane] + bh[64 + lane];
    __syncwarp();
    float c = 0.f, ov = 0.f;
    if (act) {
        float iv = gbuf[lane];
        ov = gbuf[40 + lane];
        float gv = gbuf[60 + lane];
        c = fast_sigmoid(iv) * fast_tanh(gv);
    }
    __syncwarp();
    float mu2 = warp_sum(c) * (1.f / 20.f);
    float dc = act ? (c - mu2) : 0.f;
    float var2 = warp_sum(dc * dc) * (1.f / 19.f);
    float inv2 = 1.f / (sqrtf(var2) + LN_EPS);
    float h = 0.f;
    if (act) {
        float cn = dc * inv2 * go[lane] + bo[lane];
        h = fast_sigmoid(ov) * fast_tanh(cn);
    }
    return h;
}

// ---------------- interpolation (half2 table in smem) -----------------------
__device__ __forceinline__ float interp_one_s(float xx,
                                              const unsigned int* __restrict__ tab) {
    float t = fmaf(xx, TAB_INV_STEP, TAB_T_OFF);
    t = fminf(fmaxf(t, 0.0f), TAB_T_MAX);        // clamp in t-space
    int i = __float2int_rd(t);
    float s = t - (float)i;
    unsigned int u = tab[i];                      // one LDS.32 (random banks)
    __half2 h = *reinterpret_cast<const __half2*>(&u);
    float2 q = __half22float2(h);                 // {F[i], F[i+1]}
    return fmaf(s, q.y - q.x, q.x);
}

// ---------------- the fused kernel ------------------------------------------
__global__ void __launch_bounds__(256)
fused_kernel(Weights w, const float4* __restrict__ x4, float4* __restrict__ o4,
             int n4, const float* __restrict__ x, float* __restrict__ out,
             int n) {
    __shared__ union SmemU {
        struct {
            float Wih0_s[WROWS * WPITCH];
            float Wih1_s[WROWS * WPITCH];
            float gates[8][GG];
            float hx[8][HH];
        } b;
        unsigned int tab[TAB_N];
    } smem;

    int tid = threadIdx.x, warp = tid >> 5, lane = tid & 31;
    int gtid = blockIdx.x * 256 + tid;
    int stride = gridDim.x * 256;
    const bool builder = blockIdx.x < NBUILD;

    float4 xv[VPT];
    bool vld[VPT];

    if (builder) {
        // ---- build 8 table entries (one per warp) ----
        for (int idx = tid; idx < WROWS * WPITCH; idx += 256) {
            int r = idx / WPITCH, k = idx - r * WPITCH;
            float v0 = 0.f, v1 = 0.f;
            if (r < GG && k < HH) {
                v0 = w.Wih0[r * HH + k];
                v1 = w.Wih1[r * HH + k];
            }
            smem.b.Wih0_s[idx] = v0;
            smem.b.Wih1_s[idx] = v1;
        }
        __syncthreads();

        int entry = blockIdx.x * 8 + warp;
        float xe = fmaf((float)entry, TAB_STEP, TAB_XMIN);
        const bool act = lane < HH;

        // layer 1
        float hval = 0.f;
        if (act) hval = fmaf(xe, w.W1[lane], w.b1[lane]);
        {
            float mu = warp_sum(act ? hval : 0.f) * (1.f / 20.f);
            float d = act ? (hval - mu) : 0.f;
            float var = warp_sum(d * d) * (1.f / 19.f);
            float inv = 1.f / (sqrtf(var) + LN_EPS);
            if (act) hval = fast_tanh(d * inv * w.g1[lane] + w.be1[lane]);
        }

        float v[HH];
        if (act) smem.b.hx[warp][lane] = hval;
        __syncwarp();
#pragma unroll
        for (int k = 0; k < HH; k++) v[k] = smem.b.hx[warp][k];
        __syncwarp();

        hval = cell_warp(v, smem.b.Wih0_s, w.gi0, w.bi0, w.bh0, w.go0, w.bo0,
                         smem.b.gates[warp], lane);

        if (act) smem.b.hx[warp][lane] = hval;
        __syncwarp();
#pragma unroll
        for (int k = 0; k < HH; k++) v[k] = smem.b.hx[warp][k];
        __syncwarp();

        hval = cell_warp(v, smem.b.Wih1_s, w.gi1, w.bi1, w.bh1, w.go1, w.bo1,
                         smem.b.gates[warp], lane);

        float p = act ? hval * w.Wout[lane] : 0.f;
        p = warp_sum(p);
        if (lane == 0) {
            float val = p + w.bout[0];
            __half hv = __float2half_rn(val);
            __half* H = reinterpret_cast<__half*>(g_tab_h2);
            H[2 * entry] = hv;                       // pair[entry].x
            if (entry > 0) H[2 * entry - 1] = hv;    // pair[entry-1].y
            if (entry == TAB_N - 1) H[2 * entry + 1] = hv;  // defined
        }
        __syncthreads();
        if (tid == 0) {
            __threadfence();
            atomicAdd((int*)&g_count, 1);
        }
    } else {
        // ---- front-batch x loads: DRAM fetch overlaps the build phase ----
#pragma unroll
        for (int k = 0; k < VPT; k++) {
            int idx = gtid + k * stride;
            vld[k] = idx < n4;
            if (vld[k]) xv[k] = __ldcs(&x4[idx]);
        }
    }

    // ---- grid barrier: wait for the table ----
    if (tid == 0) {
        while (g_count < NBUILD) { }
        __threadfence();
    }
    __syncthreads();

    // ---- stage 4KB half2 table into smem (one uint4 per thread) ----
    ((uint4*)smem.tab)[tid] = __ldcg(((const uint4*)g_tab_h2) + tid);
    __syncthreads();

    if (builder) {   // builders load their x batch now
#pragma unroll
        for (int k = 0; k < VPT; k++) {
            int idx = gtid + k * stride;
            vld[k] = idx < n4;
            if (vld[k]) xv[k] = __ldcs(&x4[idx]);
        }
    }

    // ---- interpolate + stream out ----
#pragma unroll
    for (int k = 0; k < VPT; k++) {
        if (!vld[k]) continue;
        float4 ov;
        ov.x = interp_one_s(xv[k].x, smem.tab);
        ov.y = interp_one_s(xv[k].y, smem.tab);
        ov.z = interp_one_s(xv[k].z, smem.tab);
        ov.w = interp_one_s(xv[k].w, smem.tab);
        __stcs(&o4[gtid + k * stride], ov);
    }

    // n % 4 tail
    if (blockIdx.x == 0 && tid < 32) {
        for (int i = n4 * 4 + tid; i < n; i += 32)
            out[i] = interp_one_s(x[i], smem.tab);
    }

    // ---- exit: last block resets the barrier counters for the next replay --
    if (tid == 0) {
        int old = atomicAdd(&g_exit, 1);
        if (old == (int)gridDim.x - 1) {
            atomicExch((int*)&g_count, 0);
            atomicExch(&g_exit, 0);
        }
    }
}

extern "C" void kernel_launch(void* const* d_in, const int* in_sizes, int n_in,
                              void* d_out, int out_size) {
    Weights w;
    w.W1 = (const float*)d_in[1];
    w.b1 = (const float*)d_in[2];
    w.g1 = (const float*)d_in[3];
    w.be1 = (const float*)d_in[4];
    w.Wih0 = (const float*)d_in[5];
    w.gi0 = (const float*)d_in[7];
    w.bi0 = (const float*)d_in[8];
    w.bh0 = (const float*)d_in[10];
    w.go0 = (const float*)d_in[11];
    w.bo0 = (const float*)d_in[12];
    w.Wih1 = (const float*)d_in[13];
    w.gi1 = (const float*)d_in[15];
    w.bi1 = (const float*)d_in[16];
    w.bh1 = (const float*)d_in[18];
    w.go1 = (const float*)d_in[19];
    w.bo1 = (const float*)d_in[20];
    w.Wout = (const float*)d_in[21];
    w.bout = (const float*)d_in[22];

    const float* x = (const float*)d_in[0];
    float* out = (float*)d_out;
    int n = in_sizes[0];
    int n4 = n / 4;

    int blocks = IBLOCKS;
    if ((long long)blocks * 256 * VPT < (long long)n4)
        blocks = (int)(((long long)n4 + 256LL * VPT - 1) / (256LL * VPT));
    if (blocks < NBUILD) blocks = NBUILD;

    fused_kernel<<<blocks, 256>>>(w, (const float4*)x, (float4*)out, n4,
                                  x, out, n);
}